// round 12
// baseline (speedup 1.0000x reference)
#include <cuda_runtime.h>

#define N_NODES 10000
#define N_EDGES 160000
#define E_HALF  80000
#define C       16
#define C2      8
#define HID     64
#define NH      2
#define NG      16
#define F_IN    64
#define F_OUT   32
#define NI      65   // intervals = HID+1

#define NPAIR       (N_NODES * NH)        // 20000
#define PAIR_BLOCKS ((NPAIR + 255) / 256) // 79
#define DIST_BLOCKS 313                   // ceil(80000/256), 2 edges/thread
#define EL_BLOCKS   625                   // 1 edge/thread, 625*256 = 160000
#define NO_BLOCKS   PAIR_BLOCKS           // 79
// back-kernel block layout: [0,79) prep | [79, 79+625) edge | [704, 783) out
#define BK_EDGE0    PAIR_BLOCKS
#define BK_OUT0     (PAIR_BLOCKS + EL_BLOCKS)
#define BK_BLOCKS   (PAIR_BLOCKS + EL_BLOCKS + NO_BLOCKS)

// ---------------- scratch (device globals; no allocations allowed) ----------
__device__ __align__(16) float g_x[N_NODES * C];                 // [n][c]
__device__ __align__(16) float g_q[N_NODES * NH * C];            // [n][h][c]
__device__ __align__(16) float g_k[N_NODES * NH * C];            // [n][h][c]
__device__ __align__(16) float g_u[N_NODES * NH * 16];           // [n][h][u0(8),u1(8)]
__device__ __align__(8) uint2 g_est[N_EDGES];                    // {bits(dist), s|t<<16}
__device__ unsigned g_dmax[N_NODES];     // max d bits per target (idempotent, 0-init)
__device__ unsigned g_dminX[N_NODES];    // max ~bits(d) per target  (~ => min d)
__device__ unsigned g_km2[NH];           // global max |k|^2 bits per head
__device__ float    g_qn2[NPAIR];        // |q|^2 per (n,h)
__device__ __align__(8) float g_mp[NPAIR];   // softmax offset m' per (n,h)
__device__ __align__(8) float    g_z[N_NODES * NH];              // [n][h]
__device__ __align__(16) float g_accp[N_NODES * NH * C2];        // projected acc [n][h][j]
__device__ float    g_pooled[NG * NH * C2];
__device__ int      g_cnt;
__device__ int      g_done_prep;
__device__ int      g_done_edge;
__device__ int      g_fast;

// piecewise-linear tables:  wv0[c](df) = S0[c] + df*S1[c];  bias(df) = A0 + df*A1
__device__ float g_t [NH][HID];      // sorted breakpoints
__device__ __align__(16) float g_S0[NH][NI][C];
__device__ __align__(16) float g_S1[NH][NI][C];
__device__ float g_A0[NH][NI];
__device__ float g_A1[NH][NI];

__device__ __forceinline__ void red_v4(float* p, float4 v) {
    asm volatile("red.global.add.v4.f32 [%0], {%1, %2, %3, %4};"
                 :: "l"(p), "f"(v.x), "f"(v.y), "f"(v.z), "f"(v.w) : "memory");
}
__device__ __forceinline__ void red_f(float* p, float v) {
    asm volatile("red.global.add.f32 [%0], %1;" :: "l"(p), "f"(v) : "memory");
}
__device__ __forceinline__ int ld_acq(const int* p) {
    int v; asm volatile("ld.global.acquire.gpu.b32 %0, [%1];" : "=r"(v) : "l"(p) : "memory");
    return v;
}
// all threads: fence; then block leader signals counter (release semantics)
__device__ __forceinline__ void block_signal(int* cnt) {
    __threadfence();
    __syncthreads();
    if (threadIdx.x == 0) atomicAdd(cnt, 1);
}
// block leader spins until counter reaches target; then fence (acquire + L1 inval)
__device__ __forceinline__ void block_wait(int* cnt, int target) {
    if (threadIdx.x == 0) {
        while (ld_acq(cnt) < target) __nanosleep(64);
        __threadfence();
    }
    __syncthreads();
}

// binary search (global-memory breakpoints)
__device__ __forceinline__ int bsearch64g(const float* t, float df) {
    int lo = 0, hi = HID;
#pragma unroll
    for (int it = 0; it < 7; it++) {
        if (lo < hi) {
            int mid = (lo + hi) >> 1;
            if (__ldg(t + mid) < df) lo = mid + 1; else hi = mid;
        }
    }
    return lo;
}

// ---------------- kernel 1: nodes + table block + edge-dist blocks ----------
__global__ void __launch_bounds__(256)
k_front(const float* __restrict__ NF,
        const float* __restrict__ We,
        const float* __restrict__ be,
        const float* __restrict__ Wq,
        const float* __restrict__ Wk,
        const float* __restrict__ W1,
        const float* __restrict__ b1,
        const float* __restrict__ Wa,
        const float* __restrict__ Wv,
        const float* __restrict__ pos,
        const int* __restrict__ ei) {
    int tid = threadIdx.x;
    int bid = blockIdx.x;

    if (bid > PAIR_BLOCKS) {
        // ---- edge geometry blocks: dist + packed s|t + per-target d range ----
        int i = (bid - PAIR_BLOCKS - 1) * 256 + tid;
        if (i >= E_HALF) return;
#pragma unroll
        for (int u = 0; u < 2; u++) {
            int e = i + u * E_HALF;
            int s = ei[e];
            int t = ei[N_EDGES + e];
            float dx = pos[3 * t + 0] - pos[3 * s + 0];
            float dy = pos[3 * t + 1] - pos[3 * s + 1];
            float dz = pos[3 * t + 2] - pos[3 * s + 2];
            float d2 = dx * dx + dy * dy + dz * dz;
            float d  = sqrtf(d2);
            unsigned db = __float_as_uint(d);     // d > 0: bit order == float order
            g_est[e] = make_uint2(db, (unsigned)s | ((unsigned)t << 16));
            atomicMax(&g_dmax[t],  db);
            atomicMax(&g_dminX[t], ~db);          // max(~bits) == min(bits)
        }
        return;
    }

    if (bid == PAIR_BLOCKS) {
        // ---- table-builder block ----
        __shared__ float raw[NH][HID];
        __shared__ float stt[NH][HID];
        if (tid == 0) { g_cnt = 0; g_done_prep = 0; g_done_edge = 0; }
        if (tid < NH * HID) {
            int h = tid / HID, j = tid % HID;
            float w = W1[h * HID + j], b = b1[h * HID + j];
            raw[h][j] = (w != 0.f) ? (-b / w) : -1e30f;  // w==0: park at -inf
        }
        __syncthreads();
        if (tid < NH * HID) {
            int h = tid / HID, j = tid % HID;
            float v = raw[h][j];
            int rank = 0;
            for (int i = 0; i < HID; i++) {
                float o = raw[h][i];
                rank += (o < v || (o == v && i < j)) ? 1 : 0;
            }
            stt[h][rank] = v;
            g_t[h][rank] = v;
        }
        __syncthreads();
        if (tid == 0) {
            int npos = 0;
            for (int h = 0; h < NH; h++)
                for (int j = 0; j < HID; j++) npos += (stt[h][j] > 0.f) ? 1 : 0;
            g_fast = (npos == 0) ? 1 : 0;
        }
        if (tid < NH * NI) {
            int h = tid / NI, i = tid % NI;
            float lo = (i == 0)   ? stt[h][0] - 1.0f       : stt[h][i - 1];
            float hi = (i == HID) ? stt[h][HID - 1] + 1.0f : stt[h][i];
            float mid = 0.5f * (lo + hi);
            float S0[C], S1[C], A0 = 0.f, A1 = 0.f;
#pragma unroll
            for (int c = 0; c < C; c++) { S0[c] = 0.f; S1[c] = 0.f; }
            for (int j = 0; j < HID; j++) {
                float w = W1[h * HID + j], b = b1[h * HID + j];
                if (fmaf(w, mid, b) > 0.f) {
                    float wa = Wa[h * HID + j];
                    A0 = fmaf(b, wa, A0);
                    A1 = fmaf(w, wa, A1);
#pragma unroll
                    for (int c = 0; c < C; c++) {
                        float wv = Wv[(h * HID + j) * (C * 3) + 3 * c]; // m=0 slice
                        S0[c] = fmaf(b, wv, S0[c]);
                        S1[c] = fmaf(w, wv, S1[c]);
                    }
                }
            }
#pragma unroll
            for (int c = 0; c < C; c++) { g_S0[h][i][c] = S0[c]; g_S1[h][i][c] = S1[c]; }
            g_A0[h][i] = A0; g_A1[h][i] = A1;
        }
        if (tid < NG * NH * C2) g_pooled[tid] = 0.f;
        return;
    }

    // ---- node-pair blocks: one thread per (n, h) ----
    __shared__ float sWe[F_IN * C];
    __shared__ float sbe[C];
    __shared__ float sWq[NH * C * C];
    __shared__ float sWk[NH * C * C];
    for (int i = tid; i < F_IN * C; i += blockDim.x) sWe[i] = We[i];
    for (int i = tid; i < C; i += blockDim.x) sbe[i] = be[i];
    for (int i = tid; i < NH * C * C; i += blockDim.x) { sWq[i] = Wq[i]; sWk[i] = Wk[i]; }
    __syncthreads();

    int gi = bid * blockDim.x + tid;
    bool valid = (gi < NPAIR);
    int n = gi >> 1;
    int h = gi & 1;
    float kn2 = 0.f;

    if (valid) {
        if (h == 0) {
            *(float2*)(g_z + n * NH) = make_float2(0.f, 0.f);
            float4 zf4 = make_float4(0.f, 0.f, 0.f, 0.f);
            float4* ac = (float4*)(g_accp + n * NH * C2);
#pragma unroll
            for (int i = 0; i < 4; i++) ac[i] = zf4;
        }

        float x[C];
#pragma unroll
        for (int j = 0; j < C; j++) x[j] = sbe[j];
        const float4* nf4 = (const float4*)(NF + n * F_IN);
#pragma unroll
        for (int i4 = 0; i4 < F_IN / 4; i4++) {
            float4 v = nf4[i4];
            float vs[4] = { v.x, v.y, v.z, v.w };
#pragma unroll
            for (int k = 0; k < 4; k++) {
                float vv = vs[k];
                int i = i4 * 4 + k;
#pragma unroll
                for (int j = 0; j < C; j++) x[j] = fmaf(vv, sWe[i * C + j], x[j]);
            }
        }
        if (h == 0) {
#pragma unroll
            for (int j = 0; j < C; j++) g_x[n * C + j] = x[j];
        }

        float q[C], k[C];
#pragma unroll
        for (int j = 0; j < C; j++) { q[j] = 0.f; k[j] = 0.f; }
#pragma unroll
        for (int i = 0; i < C; i++) {
            float xi = x[i];
#pragma unroll
            for (int j = 0; j < C; j++) {
                q[j] = fmaf(xi, sWq[h * C * C + i * C + j], q[j]);
                k[j] = fmaf(xi, sWk[h * C * C + i * C + j], k[j]);
            }
        }
        float* qp = g_q + (n * NH + h) * C;
        float* kp = g_k + (n * NH + h) * C;
        float qn2 = 0.f;
#pragma unroll
        for (int j = 0; j < C; j++) {
            qp[j] = q[j]; kp[j] = k[j];
            qn2 = fmaf(q[j], q[j], qn2);
            kn2 = fmaf(k[j], k[j], kn2);
        }
        g_qn2[gi] = qn2;
    }

    // warp parity-preserving max of kn2 (lane parity == h), lanes 0/1 commit
#pragma unroll
    for (int ofs = 16; ofs >= 2; ofs >>= 1)
        kn2 = fmaxf(kn2, __shfl_xor_sync(0xffffffffu, kn2, ofs));
    if ((tid & 31) < 2)
        atomicMax(&g_km2[h], __float_as_uint(kn2));   // kn2 >= 0: bit order ok
}

// ---------------- kernel 2: fused back end (prep -> edge -> pool/out) -------
__global__ void __launch_bounds__(256)
k_back(const int* __restrict__ batch,
       const float* __restrict__ Wo,
       const float* __restrict__ Wproj,
       const float* __restrict__ bproj,
       float* __restrict__ out) {
    int tid = threadIdx.x;
    int bid = blockIdx.x;

    // ================= PREP blocks: m' + u-vectors ===========================
    if (bid < PAIR_BLOCKS) {
        __shared__ float sWo[NH * C * C2];   // li=0 slice [h][c][j]
        for (int i = tid; i < NH * C * C2; i += blockDim.x) {
            int h = i / (C * C2);
            int r = i % (C * C2);
            sWo[i] = Wo[h * 3 * C * C2 + r];
        }
        __syncthreads();

        int gi = bid * 256 + tid;
        if (gi < NPAIR) {
            int n = gi >> 1;
            int h = gi & 1;
            int fast = g_fast;

            float mp = 0.f;
            unsigned dmb = g_dmax[n];
            if (dmb != 0u) {
                float dhi = __uint_as_float(dmb);
                float dlo = __uint_as_float(~g_dminX[n]);
                float flo, fhi;
                if (h == 0) { flo = dlo; fhi = dhi; }
                else        { flo = 1.0f / (dhi * dhi); fhi = 1.0f / (dlo * dlo); }
                int ilo = bsearch64g(&g_t[h][0], flo);
                int ihi = bsearch64g(&g_t[h][0], fhi);
                float abmax = fmaxf(fmaf(flo, __ldg(&g_A1[h][ilo]), __ldg(&g_A0[h][ilo])),
                                    fmaf(fhi, __ldg(&g_A1[h][ihi]), __ldg(&g_A0[h][ihi])));
                for (int i = ilo; i < ihi; i++) {    // interior breakpoints (empty if fast)
                    float tb = __ldg(&g_t[h][i]);
                    abmax = fmaxf(abmax, fmaf(tb, __ldg(&g_A1[h][i + 1]), __ldg(&g_A0[h][i + 1])));
                }
                float qn = sqrtf(g_qn2[gi]);
                float km = sqrtf(__uint_as_float(g_km2[h]));
                mp = abmax + qn * km * 0.25f;
            }
            g_mp[gi] = mp;

            if (fast) {
                float x[C];
                const float4* xp = (const float4*)(g_x + n * C);
#pragma unroll
                for (int i4 = 0; i4 < 4; i4++) {
                    float4 v = xp[i4];
                    x[i4 * 4 + 0] = v.x; x[i4 * 4 + 1] = v.y;
                    x[i4 * 4 + 2] = v.z; x[i4 * 4 + 3] = v.w;
                }
                const float* S0r = &g_S0[h][HID][0];
                const float* S1r = &g_S1[h][HID][0];
                float u0[C2], u1[C2];
#pragma unroll
                for (int j = 0; j < C2; j++) { u0[j] = 0.f; u1[j] = 0.f; }
#pragma unroll
                for (int c = 0; c < C; c++) {
                    float xc = x[c];
                    float s0 = __ldg(S0r + c) * xc;
                    float s1 = __ldg(S1r + c) * xc;
                    const float* wo = sWo + h * C * C2 + c * C2;
#pragma unroll
                    for (int j = 0; j < C2; j++) {
                        u0[j] = fmaf(s0, wo[j], u0[j]);
                        u1[j] = fmaf(s1, wo[j], u1[j]);
                    }
                }
                float4* up = (float4*)(g_u + gi * 16);
                up[0] = make_float4(u0[0], u0[1], u0[2], u0[3]);
                up[1] = make_float4(u0[4], u0[5], u0[6], u0[7]);
                up[2] = make_float4(u1[0], u1[1], u1[2], u1[3]);
                up[3] = make_float4(u1[4], u1[5], u1[6], u1[7]);
            }
        }
        block_signal(&g_done_prep);
        return;
    }

    // ================= EDGE blocks: logit + exp + accumulate =================
    if (bid < BK_OUT0) {
        block_wait(&g_done_prep, PAIR_BLOCKS);

        int e = (bid - BK_EDGE0) * 256 + tid;   // covers 0..159999 exactly
        int fast = g_fast;

        uint2 est = g_est[e];
        float d = __uint_as_float(est.x);
        int s = (int)(est.y & 0xffffu);
        int t = (int)(est.y >> 16);
        float d2i = 1.0f / (d * d);
        float df_h[NH] = { d, d2i };

        float2 mp2 = *(const float2*)(g_mp + t * NH);
        float mp_h[NH] = { mp2.x, mp2.y };

        if (fast) {
            float lg_h[NH];
#pragma unroll
            for (int h = 0; h < NH; h++) {
                float df = df_h[h];
                float ab = fmaf(df, g_A1[h][HID], g_A0[h][HID]);
                const float4* qt = (const float4*)(g_q + (t * NH + h) * C);
                const float4* ks = (const float4*)(g_k + (s * NH + h) * C);
                float dot = 0.f;
#pragma unroll
                for (int i4 = 0; i4 < 4; i4++) {
                    float4 a = qt[i4], b = ks[i4];
                    dot += a.x * b.x + a.y * b.y + a.z * b.z + a.w * b.w;
                }
                lg_h[h] = fmaf(dot, 0.25f, ab);
            }
            const float4* up = (const float4*)(g_u + s * NH * 16);
#pragma unroll
            for (int h = 0; h < NH; h++) {
                float ex = __expf(lg_h[h] - mp_h[h]);
                red_f(&g_z[t * NH + h], ex);
                float df = df_h[h];
                float4 u0l = up[h * 4 + 0], u0h = up[h * 4 + 1];
                float4 u1l = up[h * 4 + 2], u1h = up[h * 4 + 3];
                float4 plo, phi;
                plo.x = ex * fmaf(df, u1l.x, u0l.x);
                plo.y = ex * fmaf(df, u1l.y, u0l.y);
                plo.z = ex * fmaf(df, u1l.z, u0l.z);
                plo.w = ex * fmaf(df, u1l.w, u0l.w);
                phi.x = ex * fmaf(df, u1h.x, u0h.x);
                phi.y = ex * fmaf(df, u1h.y, u0h.y);
                phi.z = ex * fmaf(df, u1h.z, u0h.z);
                phi.w = ex * fmaf(df, u1h.w, u0h.w);
                float* accp = g_accp + (t * NH + h) * C2;
                red_v4(accp,     plo);
                red_v4(accp + 4, phi);
            }
        } else {
            // ---- general slow path (unused for this dataset) ----
            float xs[C];
            const float4* xp = (const float4*)(g_x + s * C);
#pragma unroll
            for (int i4 = 0; i4 < 4; i4++) {
                float4 v = xp[i4];
                xs[i4 * 4 + 0] = v.x; xs[i4 * 4 + 1] = v.y;
                xs[i4 * 4 + 2] = v.z; xs[i4 * 4 + 3] = v.w;
            }
#pragma unroll
            for (int h = 0; h < NH; h++) {
                float df = df_h[h];
                int idx = bsearch64g(&g_t[h][0], df);
                float ab = fmaf(df, __ldg(&g_A1[h][idx]), __ldg(&g_A0[h][idx]));
                const float4* qt = (const float4*)(g_q + (t * NH + h) * C);
                const float4* ks = (const float4*)(g_k + (s * NH + h) * C);
                float dot = 0.f;
#pragma unroll
                for (int i4 = 0; i4 < 4; i4++) {
                    float4 a = qt[i4], b = ks[i4];
                    dot += a.x * b.x + a.y * b.y + a.z * b.z + a.w * b.w;
                }
                float lg = fmaf(dot, 0.25f, ab);
                float ex = __expf(lg - mp_h[h]);
                red_f(&g_z[t * NH + h], ex);
                const float* p0 = &g_S0[h][idx][0];
                const float* p1 = &g_S1[h][idx][0];
                float p[C2];
#pragma unroll
                for (int j = 0; j < C2; j++) p[j] = 0.f;
#pragma unroll
                for (int c = 0; c < C; c++) {
                    float w = fmaf(df, __ldg(p1 + c), __ldg(p0 + c)) * xs[c];
                    const float* wo = Wo + h * 3 * C * C2 + c * C2;
#pragma unroll
                    for (int j = 0; j < C2; j++) p[j] = fmaf(w, __ldg(wo + j), p[j]);
                }
                float* accp = g_accp + (t * NH + h) * C2;
                red_v4(accp,     make_float4(ex * p[0], ex * p[1], ex * p[2], ex * p[3]));
                red_v4(accp + 4, make_float4(ex * p[4], ex * p[5], ex * p[6], ex * p[7]));
            }
        }
        block_signal(&g_done_edge);
        return;
    }

    // ================= OUT blocks: normalize + pool + final ==================
    {
        block_wait(&g_done_edge, EL_BLOCKS);

        int gi   = (bid - BK_OUT0) * 256 + tid;    // (n,h) pair index
        int lane = tid & 31;
        int n = gi >> 1;
        int h = gi & 1;
        bool valid = (gi < NPAIR);

        float v[C2];
#pragma unroll
        for (int j = 0; j < C2; j++) v[j] = 0.f;
        int g = 0;
        if (valid) {
            g = batch[n];
            float z = g_z[n * NH + h];
            if (z > 0.f) {
                float inv = 1.0f / z;
                const float4* ap = (const float4*)(g_accp + (n * NH + h) * C2);
                float4 a0 = ap[0], a1 = ap[1];
                v[0] = a0.x * inv; v[1] = a0.y * inv; v[2] = a0.z * inv; v[3] = a0.w * inv;
                v[4] = a1.x * inv; v[5] = a1.y * inv; v[6] = a1.z * inv; v[7] = a1.w * inv;
            }
        }

        int g0 = __shfl_sync(0xffffffffu, g, 0);
        bool uniform = __all_sync(0xffffffffu, valid && (g == g0));
        if (uniform) {
#pragma unroll
            for (int j = 0; j < C2; j++) {
#pragma unroll
                for (int ofs = 16; ofs >= 2; ofs >>= 1)
                    v[j] += __shfl_xor_sync(0xffffffffu, v[j], ofs);
            }
            if (lane < 2) {   // lane0: h=0 sums; lane1: h=1 sums
                float* dst = g_pooled + (g0 * NH + h) * C2;
                red_v4(dst,     make_float4(v[0], v[1], v[2], v[3]));
                red_v4(dst + 4, make_float4(v[4], v[5], v[6], v[7]));
            }
        } else if (valid) {
            float* dst = g_pooled + (g * NH + h) * C2;
#pragma unroll
            for (int jj = 0; jj < C2; jj++) {
                int j = (jj + lane) & (C2 - 1);
                red_f(dst + j, v[j]);
            }
        }

        // ---- last-out-block: fused final projection ----
        __shared__ int s_last;
        __threadfence();
        __syncthreads();
        if (tid == 0) {
            int done = atomicAdd(&g_cnt, 1);
            s_last = (done == NO_BLOCKS - 1);
        }
        __syncthreads();
        if (s_last) {
            if (tid == 0) __threadfence();
            __syncthreads();
#pragma unroll
            for (int r = 0; r < 2; r++) {
                int idx = tid + r * 256;          // 512 outputs
                int gg = idx / F_OUT;
                int oo = idx % F_OUT;
                float acc = bproj[oo];
#pragma unroll
                for (int t2 = 0; t2 < NH * C2; t2++)
                    acc = fmaf(g_pooled[gg * (NH * C2) + t2], Wproj[t2 * F_OUT + oo], acc);
                out[gg * F_OUT + oo] = acc;
            }
        }
    }
}

// ---------------- launch ----------------------------------------------------
extern "C" void kernel_launch(void* const* d_in, const int* in_sizes, int n_in,
                              void* d_out, int out_size) {
    const float* NF    = (const float*)d_in[0];
    const float* pos   = (const float*)d_in[1];
    const float* We    = (const float*)d_in[2];
    const float* be    = (const float*)d_in[3];
    const float* Wq    = (const float*)d_in[4];
    const float* Wk    = (const float*)d_in[5];
    const float* W1    = (const float*)d_in[6];
    const float* b1    = (const float*)d_in[7];
    const float* Wa    = (const float*)d_in[8];
    const float* Wv    = (const float*)d_in[9];
    const float* Wo    = (const float*)d_in[10];
    const float* Wproj = (const float*)d_in[11];
    const float* bproj = (const float*)d_in[12];
    const int*   ei    = (const int*)d_in[13];
    const int*   batch = (const int*)d_in[14];
    float* out = (float*)d_out;

    k_front<<<PAIR_BLOCKS + 1 + DIST_BLOCKS, 256>>>(NF, We, be, Wq, Wk,
                                                    W1, b1, Wa, Wv, pos, ei);
    k_back<<<BK_BLOCKS, 256>>>(batch, Wo, Wproj, bproj, out);
}

// round 13
// speedup vs baseline: 1.0565x; 1.0565x over previous
#include <cuda_runtime.h>

#define N_NODES 10000
#define N_EDGES 160000
#define E_HALF  80000
#define C       16
#define C2      8
#define HID     64
#define NH      2
#define NG      16
#define F_IN    64
#define F_OUT   32
#define NI      65   // intervals = HID+1

#define NPAIR       (N_NODES * NH)        // 20000
#define PAIR_BLOCKS ((NPAIR + 255) / 256) // 79
#define DIST_BLOCKS 313                   // ceil(80000/256), 2 edges/thread
#define EL_BLOCKS   625                   // 1 edge/thread, 625*256 = 160000
#define NO_BLOCKS   PAIR_BLOCKS           // 79

// ---------------- scratch (device globals; no allocations allowed) ----------
__device__ __align__(16) float g_x[N_NODES * C];                 // [n][c]
__device__ __align__(16) float g_q[N_NODES * NH * C];            // [n][h][c]
__device__ __align__(16) float g_k[N_NODES * NH * C];            // [n][h][c]
__device__ __align__(16) float g_u[NPAIR * 16];                  // [n*2+h][u0(8),u1(8)]
__device__ __align__(8) uint2 g_est[N_EDGES];                    // {bits(dist), s|t<<16}
__device__ unsigned g_dmaxg;             // global max d bits   (idempotent across replays)
__device__ unsigned g_dmingX;            // global max ~bits(d) (~ => min d)
__device__ unsigned g_km2[NH];           // global max |k|^2 bits per head
__device__ __align__(8) float    g_z[N_NODES * NH];              // [n][h]
__device__ __align__(16) float g_accp[N_NODES * NH * C2];        // projected acc [n][h][j]
__device__ float    g_pooled[NG * NH * C2];
__device__ int      g_cnt;
__device__ int      g_fast;

// piecewise-linear tables (slow fallback path only)
__device__ float g_t [NH][HID];      // sorted breakpoints
__device__ __align__(16) float g_S0[NH][NI][C];
__device__ __align__(16) float g_S1[NH][NI][C];
__device__ float g_A0[NH][NI];
__device__ float g_A1[NH][NI];

__device__ __forceinline__ void red_v4(float* p, float4 v) {
    asm volatile("red.global.add.v4.f32 [%0], {%1, %2, %3, %4};"
                 :: "l"(p), "f"(v.x), "f"(v.y), "f"(v.z), "f"(v.w) : "memory");
}
__device__ __forceinline__ void red_f(float* p, float v) {
    asm volatile("red.global.add.f32 [%0], %1;" :: "l"(p), "f"(v) : "memory");
}

// binary search (global-memory breakpoints; slow path only)
__device__ __forceinline__ int bsearch64g(const float* t, float df) {
    int lo = 0, hi = HID;
#pragma unroll
    for (int it = 0; it < 7; it++) {
        if (lo < hi) {
            int mid = (lo + hi) >> 1;
            if (__ldg(t + mid) < df) lo = mid + 1; else hi = mid;
        }
    }
    return lo;
}

// ---------------- kernel 1: nodes(+u) + table block + edge-dist blocks ------
__global__ void __launch_bounds__(256)
k_front(const float* __restrict__ NF,
        const float* __restrict__ We,
        const float* __restrict__ be,
        const float* __restrict__ Wq,
        const float* __restrict__ Wk,
        const float* __restrict__ W1,
        const float* __restrict__ b1,
        const float* __restrict__ Wa,
        const float* __restrict__ Wv,
        const float* __restrict__ Wo,
        const float* __restrict__ pos,
        const int* __restrict__ ei) {
    int tid = threadIdx.x;
    int bid = blockIdx.x;

    if (bid > PAIR_BLOCKS) {
        // ---- edge geometry blocks: dist + packed s|t + GLOBAL d-range ------
        int i = (bid - PAIR_BLOCKS - 1) * 256 + tid;
        unsigned lmax = 0u, lminX = 0u;
        if (i < E_HALF) {
#pragma unroll
            for (int u = 0; u < 2; u++) {
                int e = i + u * E_HALF;
                int s = ei[e];
                int t = ei[N_EDGES + e];
                float dx = pos[3 * t + 0] - pos[3 * s + 0];
                float dy = pos[3 * t + 1] - pos[3 * s + 1];
                float dz = pos[3 * t + 2] - pos[3 * s + 2];
                float d2 = dx * dx + dy * dy + dz * dz;
                float d  = sqrtf(d2);
                unsigned db = __float_as_uint(d);    // d > 0: bit order == float order
                g_est[e] = make_uint2(db, (unsigned)s | ((unsigned)t << 16));
                lmax  = max(lmax, db);
                lminX = max(lminX, ~db);
            }
        }
        // warp reduce then 1 atomic per warp per counter
#pragma unroll
        for (int ofs = 16; ofs >= 1; ofs >>= 1) {
            lmax  = max(lmax,  __shfl_xor_sync(0xffffffffu, lmax,  ofs));
            lminX = max(lminX, __shfl_xor_sync(0xffffffffu, lminX, ofs));
        }
        if ((tid & 31) == 0) {
            atomicMax(&g_dmaxg,  lmax);
            atomicMax(&g_dmingX, lminX);
        }
        return;
    }

    if (bid == PAIR_BLOCKS) {
        // ---- table-builder block (slow-path tables + fast flag) ----
        __shared__ float raw[NH][HID];
        __shared__ float stt[NH][HID];
        if (tid == 0) g_cnt = 0;
        if (tid < NH * HID) {
            int h = tid / HID, j = tid % HID;
            float w = W1[h * HID + j], b = b1[h * HID + j];
            raw[h][j] = (w != 0.f) ? (-b / w) : -1e30f;  // w==0: park at -inf
        }
        __syncthreads();
        if (tid < NH * HID) {
            int h = tid / HID, j = tid % HID;
            float v = raw[h][j];
            int rank = 0;
            for (int i = 0; i < HID; i++) {
                float o = raw[h][i];
                rank += (o < v || (o == v && i < j)) ? 1 : 0;
            }
            stt[h][rank] = v;
            g_t[h][rank] = v;
        }
        __syncthreads();
        if (tid == 0) {
            int npos = 0;
            for (int h = 0; h < NH; h++)
                for (int j = 0; j < HID; j++) npos += (stt[h][j] > 0.f) ? 1 : 0;
            g_fast = (npos == 0) ? 1 : 0;
        }
        if (tid < NH * NI) {
            int h = tid / NI, i = tid % NI;
            float lo = (i == 0)   ? stt[h][0] - 1.0f       : stt[h][i - 1];
            float hi = (i == HID) ? stt[h][HID - 1] + 1.0f : stt[h][i];
            float mid = 0.5f * (lo + hi);
            float S0[C], S1[C], A0 = 0.f, A1 = 0.f;
#pragma unroll
            for (int c = 0; c < C; c++) { S0[c] = 0.f; S1[c] = 0.f; }
            for (int j = 0; j < HID; j++) {
                float w = W1[h * HID + j], b = b1[h * HID + j];
                bool act;
                if (i == HID) act = (w > 0.f) || (w == 0.f && b > 0.f);  // exact top-interval rule
                else          act = fmaf(w, mid, b) > 0.f;
                if (act) {
                    float wa = Wa[h * HID + j];
                    A0 = fmaf(b, wa, A0);
                    A1 = fmaf(w, wa, A1);
#pragma unroll
                    for (int c = 0; c < C; c++) {
                        float wv = Wv[(h * HID + j) * (C * 3) + 3 * c]; // m=0 slice
                        S0[c] = fmaf(b, wv, S0[c]);
                        S1[c] = fmaf(w, wv, S1[c]);
                    }
                }
            }
#pragma unroll
            for (int c = 0; c < C; c++) { g_S0[h][i][c] = S0[c]; g_S1[h][i][c] = S1[c]; }
            g_A0[h][i] = A0; g_A1[h][i] = A1;
        }
        if (tid < NG * NH * C2) g_pooled[tid] = 0.f;
        return;
    }

    // ---- node-pair blocks: one thread per (n, h); also computes u-vectors --
    __shared__ float sWe[F_IN * C];
    __shared__ float sbe[C];
    __shared__ float sWq[NH * C * C];
    __shared__ float sWk[NH * C * C];
    __shared__ float sWo[NH * C * C2];        // li=0 slice [h][c][j]
    __shared__ float sS0f[NH][C], sS1f[NH][C]; // fast-path (top-interval) rows
    for (int i = tid; i < F_IN * C; i += blockDim.x) sWe[i] = We[i];
    for (int i = tid; i < C; i += blockDim.x) sbe[i] = be[i];
    for (int i = tid; i < NH * C * C; i += blockDim.x) { sWq[i] = Wq[i]; sWk[i] = Wk[i]; }
    for (int i = tid; i < NH * C * C2; i += blockDim.x) {
        int h = i / (C * C2);
        int r = i % (C * C2);
        sWo[i] = Wo[h * 3 * C * C2 + r];
    }
    if (tid < NH * C) {
        int h = tid / C, c = tid % C;
        float s0 = 0.f, s1 = 0.f;
        for (int j = 0; j < HID; j++) {
            float w = W1[h * HID + j], b = b1[h * HID + j];
            if ((w > 0.f) || (w == 0.f && b > 0.f)) {   // active as df -> +inf
                float wv = Wv[(h * HID + j) * (C * 3) + 3 * c];
                s0 = fmaf(b, wv, s0);
                s1 = fmaf(w, wv, s1);
            }
        }
        sS0f[h][c] = s0;
        sS1f[h][c] = s1;
    }
    __syncthreads();

    int gi = bid * blockDim.x + tid;
    bool valid = (gi < NPAIR);
    int n = gi >> 1;
    int h = gi & 1;
    float kn2 = 0.f;

    if (valid) {
        if (h == 0) {
            *(float2*)(g_z + n * NH) = make_float2(0.f, 0.f);
            float4 zf4 = make_float4(0.f, 0.f, 0.f, 0.f);
            float4* ac = (float4*)(g_accp + n * NH * C2);
#pragma unroll
            for (int i = 0; i < 4; i++) ac[i] = zf4;
        }

        float x[C];
#pragma unroll
        for (int j = 0; j < C; j++) x[j] = sbe[j];
        const float4* nf4 = (const float4*)(NF + n * F_IN);
#pragma unroll
        for (int i4 = 0; i4 < F_IN / 4; i4++) {
            float4 v = nf4[i4];
            float vs[4] = { v.x, v.y, v.z, v.w };
#pragma unroll
            for (int k = 0; k < 4; k++) {
                float vv = vs[k];
                int i = i4 * 4 + k;
#pragma unroll
                for (int j = 0; j < C; j++) x[j] = fmaf(vv, sWe[i * C + j], x[j]);
            }
        }
        if (h == 0) {
#pragma unroll
            for (int j = 0; j < C; j++) g_x[n * C + j] = x[j];
        }

        float q[C], k[C];
#pragma unroll
        for (int j = 0; j < C; j++) { q[j] = 0.f; k[j] = 0.f; }
#pragma unroll
        for (int i = 0; i < C; i++) {
            float xi = x[i];
#pragma unroll
            for (int j = 0; j < C; j++) {
                q[j] = fmaf(xi, sWq[h * C * C + i * C + j], q[j]);
                k[j] = fmaf(xi, sWk[h * C * C + i * C + j], k[j]);
            }
        }
        float* qp = g_q + gi * C;
        float* kp = g_k + gi * C;
#pragma unroll
        for (int j = 0; j < C; j++) {
            qp[j] = q[j]; kp[j] = k[j];
            kn2 = fmaf(k[j], k[j], kn2);
        }

        // u-vectors (fast path): u0/u1[j] = sum_c Sf[c]*x[c]*Wo[c][j]
        float u0[C2], u1[C2];
#pragma unroll
        for (int j = 0; j < C2; j++) { u0[j] = 0.f; u1[j] = 0.f; }
#pragma unroll
        for (int c = 0; c < C; c++) {
            float xc = x[c];
            float s0 = sS0f[h][c] * xc;
            float s1 = sS1f[h][c] * xc;
            const float* wo = sWo + h * C * C2 + c * C2;
#pragma unroll
            for (int j = 0; j < C2; j++) {
                u0[j] = fmaf(s0, wo[j], u0[j]);
                u1[j] = fmaf(s1, wo[j], u1[j]);
            }
        }
        float4* up = (float4*)(g_u + gi * 16);
        up[0] = make_float4(u0[0], u0[1], u0[2], u0[3]);
        up[1] = make_float4(u0[4], u0[5], u0[6], u0[7]);
        up[2] = make_float4(u1[0], u1[1], u1[2], u1[3]);
        up[3] = make_float4(u1[4], u1[5], u1[6], u1[7]);
    }

    // warp parity-preserving max of kn2 (lane parity == h), lanes 0/1 commit
#pragma unroll
    for (int ofs = 16; ofs >= 2; ofs >>= 1)
        kn2 = fmaxf(kn2, __shfl_xor_sync(0xffffffffu, kn2, ofs));
    if ((tid & 31) < 2)
        atomicMax(&g_km2[h], __float_as_uint(kn2));   // kn2 >= 0: bit order ok
}

// ---------------- kernel 2: SINGLE edge pass (inline m' bound) --------------
__global__ void __launch_bounds__(256)
k_edge(const float* __restrict__ Wo) {
    int e = blockIdx.x * blockDim.x + threadIdx.x;   // 625*256 == 160000
    int fast = g_fast;

    uint2 est = g_est[e];
    float d = __uint_as_float(est.x);
    int s = (int)(est.y & 0xffffu);
    int t = (int)(est.y >> 16);
    float d2i = 1.0f / (d * d);
    float df_h[NH] = { d, d2i };

    // global d-range -> per-head df-range
    float dhi = __uint_as_float(g_dmaxg);
    float dlo = __uint_as_float(~g_dmingX);
    float flo_h[NH] = { dlo, 1.0f / (dhi * dhi) };
    float fhi_h[NH] = { dhi, 1.0f / (dlo * dlo) };
    float km_h[NH]  = { sqrtf(__uint_as_float(g_km2[0])),
                        sqrtf(__uint_as_float(g_km2[1])) };

    if (fast) {
        float lg_h[NH], mp_h[NH];
#pragma unroll
        for (int h = 0; h < NH; h++) {
            float df = df_h[h];
            float A0 = g_A0[h][HID], A1 = g_A1[h][HID];
            float ab = fmaf(df, A1, A0);
            const float4* qt = (const float4*)(g_q + (t * NH + h) * C);
            const float4* ks = (const float4*)(g_k + (s * NH + h) * C);
            float dot = 0.f, qn2 = 0.f;
#pragma unroll
            for (int i4 = 0; i4 < 4; i4++) {
                float4 a = qt[i4], b = ks[i4];
                dot += a.x * b.x + a.y * b.y + a.z * b.z + a.w * b.w;
                qn2 += a.x * a.x + a.y * a.y + a.z * a.z + a.w * a.w;
            }
            lg_h[h] = fmaf(dot, 0.25f, ab);
            float abmax = fmaxf(fmaf(flo_h[h], A1, A0), fmaf(fhi_h[h], A1, A0));
            mp_h[h] = abmax + sqrtf(qn2) * km_h[h] * 0.25f;
        }
        const float4* up = (const float4*)(g_u + s * NH * 16);
#pragma unroll
        for (int h = 0; h < NH; h++) {
            float ex = __expf(lg_h[h] - mp_h[h]);
            red_f(&g_z[t * NH + h], ex);
            float df = df_h[h];
            float4 u0l = up[h * 4 + 0], u0h = up[h * 4 + 1];
            float4 u1l = up[h * 4 + 2], u1h = up[h * 4 + 3];
            float4 plo, phi;
            plo.x = ex * fmaf(df, u1l.x, u0l.x);
            plo.y = ex * fmaf(df, u1l.y, u0l.y);
            plo.z = ex * fmaf(df, u1l.z, u0l.z);
            plo.w = ex * fmaf(df, u1l.w, u0l.w);
            phi.x = ex * fmaf(df, u1h.x, u0h.x);
            phi.y = ex * fmaf(df, u1h.y, u0h.y);
            phi.z = ex * fmaf(df, u1h.z, u0h.z);
            phi.w = ex * fmaf(df, u1h.w, u0h.w);
            float* accp = g_accp + (t * NH + h) * C2;
            red_v4(accp,     plo);
            red_v4(accp + 4, phi);
        }
        return;
    }

    // ---- general slow path (per-edge table walk; unused for this dataset) ---
    float xs[C];
    {
        const float4* xp = (const float4*)(g_x + s * C);
#pragma unroll
        for (int i4 = 0; i4 < 4; i4++) {
            float4 v = xp[i4];
            xs[i4 * 4 + 0] = v.x; xs[i4 * 4 + 1] = v.y;
            xs[i4 * 4 + 2] = v.z; xs[i4 * 4 + 3] = v.w;
        }
    }
#pragma unroll
    for (int h = 0; h < NH; h++) {
        float df = df_h[h];
        int idx = bsearch64g(&g_t[h][0], df);
        float ab = fmaf(df, __ldg(&g_A1[h][idx]), __ldg(&g_A0[h][idx]));
        const float4* qt = (const float4*)(g_q + (t * NH + h) * C);
        const float4* ks = (const float4*)(g_k + (s * NH + h) * C);
        float dot = 0.f, qn2 = 0.f;
#pragma unroll
        for (int i4 = 0; i4 < 4; i4++) {
            float4 a = qt[i4], b = ks[i4];
            dot += a.x * b.x + a.y * b.y + a.z * b.z + a.w * b.w;
            qn2 += a.x * a.x + a.y * a.y + a.z * a.z + a.w * a.w;
        }
        float lg = fmaf(dot, 0.25f, ab);

        // abmax over global df-range: endpoints + interior breakpoints
        float flo = flo_h[h], fhi = fhi_h[h];
        int ilo = bsearch64g(&g_t[h][0], flo);
        int ihi = bsearch64g(&g_t[h][0], fhi);
        float abmax = fmaxf(fmaf(flo, __ldg(&g_A1[h][ilo]), __ldg(&g_A0[h][ilo])),
                            fmaf(fhi, __ldg(&g_A1[h][ihi]), __ldg(&g_A0[h][ihi])));
        for (int i = ilo; i < ihi; i++) {
            float tb = __ldg(&g_t[h][i]);
            abmax = fmaxf(abmax, fmaf(tb, __ldg(&g_A1[h][i + 1]), __ldg(&g_A0[h][i + 1])));
        }
        float mp = abmax + sqrtf(qn2) * km_h[h] * 0.25f;

        float ex = __expf(lg - mp);
        red_f(&g_z[t * NH + h], ex);
        const float* p0 = &g_S0[h][idx][0];
        const float* p1 = &g_S1[h][idx][0];
        float p[C2];
#pragma unroll
        for (int j = 0; j < C2; j++) p[j] = 0.f;
#pragma unroll
        for (int c = 0; c < C; c++) {
            float w = fmaf(df, __ldg(p1 + c), __ldg(p0 + c)) * xs[c];
            const float* wo = Wo + h * 3 * C * C2 + c * C2;
#pragma unroll
            for (int j = 0; j < C2; j++) p[j] = fmaf(w, __ldg(wo + j), p[j]);
        }
        float* accp = g_accp + (t * NH + h) * C2;
        red_v4(accp,     make_float4(ex * p[0], ex * p[1], ex * p[2], ex * p[3]));
        red_v4(accp + 4, make_float4(ex * p[4], ex * p[5], ex * p[6], ex * p[7]));
    }
}

// ---------------- kernel 3: normalize + pool + fused final projection -------
__global__ void __launch_bounds__(256)
k_node_out(const int* __restrict__ batch,
           const float* __restrict__ Wproj,
           const float* __restrict__ bproj,
           float* __restrict__ out) {
    int tid  = threadIdx.x;
    int gi   = blockIdx.x * blockDim.x + tid;      // (n,h) pair index
    int lane = tid & 31;

    int n = gi >> 1;
    int h = gi & 1;
    bool valid = (gi < NPAIR);

    float v[C2];
#pragma unroll
    for (int j = 0; j < C2; j++) v[j] = 0.f;
    int g = 0;
    if (valid) {
        g = batch[n];
        float z = g_z[n * NH + h];
        if (z > 0.f) {
            float inv = 1.0f / z;
            const float4* ap = (const float4*)(g_accp + (n * NH + h) * C2);
            float4 a0 = ap[0], a1 = ap[1];
            v[0] = a0.x * inv; v[1] = a0.y * inv; v[2] = a0.z * inv; v[3] = a0.w * inv;
            v[4] = a1.x * inv; v[5] = a1.y * inv; v[6] = a1.z * inv; v[7] = a1.w * inv;
        }
    }

    int g0 = __shfl_sync(0xffffffffu, g, 0);
    bool uniform = __all_sync(0xffffffffu, valid && (g == g0));
    if (uniform) {
#pragma unroll
        for (int j = 0; j < C2; j++) {
#pragma unroll
            for (int ofs = 16; ofs >= 2; ofs >>= 1)
                v[j] += __shfl_xor_sync(0xffffffffu, v[j], ofs);
        }
        if (lane < 2) {   // lane0: h=0 sums; lane1: h=1 sums
            float* dst = g_pooled + (g0 * NH + h) * C2;
            red_v4(dst,     make_float4(v[0], v[1], v[2], v[3]));
            red_v4(dst + 4, make_float4(v[4], v[5], v[6], v[7]));
        }
    } else if (valid) {
        float* dst = g_pooled + (g * NH + h) * C2;
#pragma unroll
        for (int jj = 0; jj < C2; jj++) {
            int j = (jj + lane) & (C2 - 1);
            red_f(dst + j, v[j]);
        }
    }

    // ---- last-block-done: fused final projection ----
    __shared__ int s_last;
    __threadfence();
    if (tid == 0) {
        int done = atomicAdd(&g_cnt, 1);
        s_last = (done == NO_BLOCKS - 1);
    }
    __syncthreads();
    if (s_last) {
        __threadfence();
#pragma unroll
        for (int r = 0; r < 2; r++) {
            int idx = tid + r * 256;          // 512 outputs
            int gg = idx / F_OUT;
            int oo = idx % F_OUT;
            float acc = bproj[oo];
#pragma unroll
            for (int t2 = 0; t2 < NH * C2; t2++)
                acc = fmaf(g_pooled[gg * (NH * C2) + t2], Wproj[t2 * F_OUT + oo], acc);
            out[gg * F_OUT + oo] = acc;
        }
    }
}

// ---------------- launch ----------------------------------------------------
extern "C" void kernel_launch(void* const* d_in, const int* in_sizes, int n_in,
                              void* d_out, int out_size) {
    const float* NF    = (const float*)d_in[0];
    const float* pos   = (const float*)d_in[1];
    const float* We    = (const float*)d_in[2];
    const float* be    = (const float*)d_in[3];
    const float* Wq    = (const float*)d_in[4];
    const float* Wk    = (const float*)d_in[5];
    const float* W1    = (const float*)d_in[6];
    const float* b1    = (const float*)d_in[7];
    const float* Wa    = (const float*)d_in[8];
    const float* Wv    = (const float*)d_in[9];
    const float* Wo    = (const float*)d_in[10];
    const float* Wproj = (const float*)d_in[11];
    const float* bproj = (const float*)d_in[12];
    const int*   ei    = (const int*)d_in[13];
    const int*   batch = (const int*)d_in[14];
    float* out = (float*)d_out;

    k_front<<<PAIR_BLOCKS + 1 + DIST_BLOCKS, 256>>>(NF, We, be, Wq, Wk,
                                                    W1, b1, Wa, Wv, Wo, pos, ei);
    k_edge<<<EL_BLOCKS, 256>>>(Wo);
    k_node_out<<<NO_BLOCKS, 256>>>(batch, Wproj, bproj, out);
}

// round 14
// speedup vs baseline: 1.4115x; 1.3360x over previous
#include <cuda_runtime.h>

#define N_NODES 10000
#define N_EDGES 160000
#define E_HALF  80000
#define C       16
#define C2      8
#define HID     64
#define NH      2
#define NG      16
#define F_IN    64
#define F_OUT   32
#define NI      65   // intervals = HID+1

#define NPAIR       (N_NODES * NH)        // 20000
#define PAIR_BLOCKS ((NPAIR + 255) / 256) // 79
#define DIST_BLOCKS 313                   // ceil(80000/256), 2 edges/thread
#define EL_BLOCKS   625                   // 1 edge/thread, 625*256 = 160000
#define NO_BLOCKS   PAIR_BLOCKS           // 79

// ---------------- scratch (device globals; no allocations allowed) ----------
__device__ __align__(16) float g_x[N_NODES * C];                 // [n][c]
__device__ __align__(16) float g_q[N_NODES * NH * C];            // [n][h][c]
__device__ __align__(16) float g_k[N_NODES * NH * C];            // [n][h][c]
__device__ __align__(16) float g_u[NPAIR * 16];                  // [n*2+h][u0(8),u1(8)]
__device__ __align__(8) uint2 g_est[N_EDGES];                    // {bits(dist), s|t<<16}
__device__ unsigned g_dmaxg;             // global max d bits   (idempotent across replays)
__device__ unsigned g_dmingX;            // global max ~bits(d) (~ => min d)
__device__ unsigned g_km2[NH];           // global max |k|^2 bits per head
__device__ __align__(8) float    g_z[N_NODES * NH];              // [n][h]
__device__ __align__(16) float g_accp[N_NODES * NH * C2];        // projected acc [n][h][j]
__device__ float    g_pooled[NG * NH * C2];
__device__ int      g_cnt;
__device__ int      g_fast;

// piecewise-linear tables (slow fallback path only)
__device__ float g_t [NH][HID];      // sorted breakpoints
__device__ __align__(16) float g_S0[NH][NI][C];
__device__ __align__(16) float g_S1[NH][NI][C];
__device__ float g_A0[NH][NI];
__device__ float g_A1[NH][NI];

__device__ __forceinline__ void red_v4(float* p, float4 v) {
    asm volatile("red.global.add.v4.f32 [%0], {%1, %2, %3, %4};"
                 :: "l"(p), "f"(v.x), "f"(v.y), "f"(v.z), "f"(v.w) : "memory");
}
__device__ __forceinline__ void red_f(float* p, float v) {
    asm volatile("red.global.add.f32 [%0], %1;" :: "l"(p), "f"(v) : "memory");
}

// binary search (global-memory breakpoints; slow path only)
__device__ __forceinline__ int bsearch64g(const float* t, float df) {
    int lo = 0, hi = HID;
#pragma unroll
    for (int it = 0; it < 7; it++) {
        if (lo < hi) {
            int mid = (lo + hi) >> 1;
            if (__ldg(t + mid) < df) lo = mid + 1; else hi = mid;
        }
    }
    return lo;
}

// ---------------- kernel 1: nodes(+u) + table block + edge-dist blocks ------
__global__ void __launch_bounds__(256)
k_front(const float* __restrict__ NF,
        const float* __restrict__ We,
        const float* __restrict__ be,
        const float* __restrict__ Wq,
        const float* __restrict__ Wk,
        const float* __restrict__ W1,
        const float* __restrict__ b1,
        const float* __restrict__ Wa,
        const float* __restrict__ Wv,
        const float* __restrict__ Wo,
        const float* __restrict__ pos,
        const int* __restrict__ ei) {
    int tid = threadIdx.x;
    int bid = blockIdx.x;

    if (bid > PAIR_BLOCKS) {
        // ---- edge geometry blocks: dist + packed s|t + GLOBAL d-range ------
        int i = (bid - PAIR_BLOCKS - 1) * 256 + tid;
        unsigned lmax = 0u, lminX = 0u;
        if (i < E_HALF) {
#pragma unroll
            for (int u = 0; u < 2; u++) {
                int e = i + u * E_HALF;
                int s = ei[e];
                int t = ei[N_EDGES + e];
                float dx = pos[3 * t + 0] - pos[3 * s + 0];
                float dy = pos[3 * t + 1] - pos[3 * s + 1];
                float dz = pos[3 * t + 2] - pos[3 * s + 2];
                float d2 = dx * dx + dy * dy + dz * dz;
                float d  = sqrtf(d2);
                unsigned db = __float_as_uint(d);    // d > 0: bit order == float order
                g_est[e] = make_uint2(db, (unsigned)s | ((unsigned)t << 16));
                lmax  = max(lmax, db);
                lminX = max(lminX, ~db);
            }
        }
        // warp reduce then 1 atomic per warp per counter
#pragma unroll
        for (int ofs = 16; ofs >= 1; ofs >>= 1) {
            lmax  = max(lmax,  __shfl_xor_sync(0xffffffffu, lmax,  ofs));
            lminX = max(lminX, __shfl_xor_sync(0xffffffffu, lminX, ofs));
        }
        if ((tid & 31) == 0) {
            atomicMax(&g_dmaxg,  lmax);
            atomicMax(&g_dmingX, lminX);
        }
        return;
    }

    if (bid == PAIR_BLOCKS) {
        // ---- table block: fast detection + (fast: top-interval only) -------
        __shared__ int s_fast;
        __shared__ unsigned sany[8];
        __shared__ float sA0w[4], sA1w[4];
        if (tid == 0) g_cnt = 0;

        int pos_bp = 0;
        if (tid < NH * HID) {
            int h = tid / HID, j = tid % HID;
            float w = W1[h * HID + j], b = b1[h * HID + j];
            pos_bp = (w != 0.f) && ((-b / w) > 0.f);   // breakpoint strictly > 0?
        }
        unsigned any = __ballot_sync(0xffffffffu, pos_bp);
        if ((tid & 31) == 0) sany[tid >> 5] = any;
        __syncthreads();
        if (tid == 0) {
            unsigned tot = 0;
            for (int wgi = 0; wgi < 8; wgi++) tot |= sany[wgi];
            s_fast = (tot == 0u) ? 1 : 0;
            g_fast = s_fast;
        }
        __syncthreads();

        if (s_fast) {
            // only A0/A1 at top interval are consumed by the fast path
            float a0 = 0.f, a1 = 0.f;
            if (tid < NH * HID) {
                int h = tid / HID, j = tid % HID;
                float w = W1[h * HID + j], b = b1[h * HID + j];
                if ((w > 0.f) || (w == 0.f && b > 0.f)) {   // active as df -> +inf
                    float wa = Wa[h * HID + j];
                    a0 = b * wa;
                    a1 = w * wa;
                }
            }
#pragma unroll
            for (int ofs = 16; ofs >= 1; ofs >>= 1) {
                a0 += __shfl_xor_sync(0xffffffffu, a0, ofs);
                a1 += __shfl_xor_sync(0xffffffffu, a1, ofs);
            }
            if ((tid & 31) == 0 && tid < 128) { sA0w[tid >> 5] = a0; sA1w[tid >> 5] = a1; }
            __syncthreads();
            if (tid < NH) {
                g_A0[tid][HID] = sA0w[tid * 2] + sA0w[tid * 2 + 1];
                g_A1[tid][HID] = sA1w[tid * 2] + sA1w[tid * 2 + 1];
            }
        } else {
            // ---- full table build (slow path; not taken for this dataset) ----
            __shared__ float raw[NH][HID];
            __shared__ float stt[NH][HID];
            if (tid < NH * HID) {
                int h = tid / HID, j = tid % HID;
                float w = W1[h * HID + j], b = b1[h * HID + j];
                raw[h][j] = (w != 0.f) ? (-b / w) : -1e30f;
            }
            __syncthreads();
            if (tid < NH * HID) {
                int h = tid / HID, j = tid % HID;
                float v = raw[h][j];
                int rank = 0;
                for (int i = 0; i < HID; i++) {
                    float o = raw[h][i];
                    rank += (o < v || (o == v && i < j)) ? 1 : 0;
                }
                stt[h][rank] = v;
                g_t[h][rank] = v;
            }
            __syncthreads();
            if (tid < NH * NI) {
                int h = tid / NI, i = tid % NI;
                float lo = (i == 0)   ? stt[h][0] - 1.0f       : stt[h][i - 1];
                float hi = (i == HID) ? stt[h][HID - 1] + 1.0f : stt[h][i];
                float mid = 0.5f * (lo + hi);
                float S0[C], S1[C], A0 = 0.f, A1 = 0.f;
#pragma unroll
                for (int c = 0; c < C; c++) { S0[c] = 0.f; S1[c] = 0.f; }
                for (int j = 0; j < HID; j++) {
                    float w = W1[h * HID + j], b = b1[h * HID + j];
                    bool act;
                    if (i == HID) act = (w > 0.f) || (w == 0.f && b > 0.f);
                    else          act = fmaf(w, mid, b) > 0.f;
                    if (act) {
                        float wa = Wa[h * HID + j];
                        A0 = fmaf(b, wa, A0);
                        A1 = fmaf(w, wa, A1);
#pragma unroll
                        for (int c = 0; c < C; c++) {
                            float wv = Wv[(h * HID + j) * (C * 3) + 3 * c];
                            S0[c] = fmaf(b, wv, S0[c]);
                            S1[c] = fmaf(w, wv, S1[c]);
                        }
                    }
                }
#pragma unroll
                for (int c = 0; c < C; c++) { g_S0[h][i][c] = S0[c]; g_S1[h][i][c] = S1[c]; }
                g_A0[h][i] = A0; g_A1[h][i] = A1;
            }
        }
        if (tid < NG * NH * C2) g_pooled[tid] = 0.f;
        return;
    }

    // ---- node-pair blocks: one thread per (n, h); also computes u-vectors --
    __shared__ float sWe[F_IN * C];
    __shared__ float sbe[C];
    __shared__ float sWq[NH * C * C];
    __shared__ float sWk[NH * C * C];
    __shared__ float sWo[NH * C * C2];            // li=0 slice [h][c][j]
    __shared__ float sP0[NH][C][8], sP1[NH][C][8]; // partials for fast S rows
    __shared__ float sS0f[NH][C], sS1f[NH][C];     // fast-path (top-interval) rows
    for (int i = tid; i < F_IN * C; i += blockDim.x) sWe[i] = We[i];
    for (int i = tid; i < C; i += blockDim.x) sbe[i] = be[i];
    for (int i = tid; i < NH * C * C; i += blockDim.x) { sWq[i] = Wq[i]; sWk[i] = Wk[i]; }
    for (int i = tid; i < NH * C * C2; i += blockDim.x) {
        int h = i / (C * C2);
        int r = i % (C * C2);
        sWo[i] = Wo[h * 3 * C * C2 + r];
    }
    {
        // parallel fast-S-row build: thread = (h, c, jgroup of 8)
        int h  = tid >> 7;            // 0..1
        int c  = (tid >> 3) & 15;     // 0..15
        int gq = tid & 7;             // 0..7
        float p0 = 0.f, p1 = 0.f;
#pragma unroll
        for (int jj = 0; jj < 8; jj++) {
            int j = gq * 8 + jj;
            float w = W1[h * HID + j], b = b1[h * HID + j];
            if ((w > 0.f) || (w == 0.f && b > 0.f)) {   // active as df -> +inf
                float wv = Wv[(h * HID + j) * (C * 3) + 3 * c];
                p0 = fmaf(b, wv, p0);
                p1 = fmaf(w, wv, p1);
            }
        }
        sP0[h][c][gq] = p0;
        sP1[h][c][gq] = p1;
    }
    __syncthreads();
    if (tid < NH * C) {
        int h = tid / C, c = tid % C;
        float s0 = 0.f, s1 = 0.f;
#pragma unroll
        for (int gq = 0; gq < 8; gq++) { s0 += sP0[h][c][gq]; s1 += sP1[h][c][gq]; }
        sS0f[h][c] = s0;
        sS1f[h][c] = s1;
    }
    __syncthreads();

    int gi = bid * blockDim.x + tid;
    bool valid = (gi < NPAIR);
    int n = gi >> 1;
    int h = gi & 1;
    float kn2 = 0.f;

    if (valid) {
        if (h == 0) {
            *(float2*)(g_z + n * NH) = make_float2(0.f, 0.f);
            float4 zf4 = make_float4(0.f, 0.f, 0.f, 0.f);
            float4* ac = (float4*)(g_accp + n * NH * C2);
#pragma unroll
            for (int i = 0; i < 4; i++) ac[i] = zf4;
        }

        float x[C];
#pragma unroll
        for (int j = 0; j < C; j++) x[j] = sbe[j];
        const float4* nf4 = (const float4*)(NF + n * F_IN);
#pragma unroll
        for (int i4 = 0; i4 < F_IN / 4; i4++) {
            float4 v = nf4[i4];
            float vs[4] = { v.x, v.y, v.z, v.w };
#pragma unroll
            for (int k = 0; k < 4; k++) {
                float vv = vs[k];
                int i = i4 * 4 + k;
#pragma unroll
                for (int j = 0; j < C; j++) x[j] = fmaf(vv, sWe[i * C + j], x[j]);
            }
        }
        if (h == 0) {
#pragma unroll
            for (int j = 0; j < C; j++) g_x[n * C + j] = x[j];
        }

        float q[C], k[C];
#pragma unroll
        for (int j = 0; j < C; j++) { q[j] = 0.f; k[j] = 0.f; }
#pragma unroll
        for (int i = 0; i < C; i++) {
            float xi = x[i];
#pragma unroll
            for (int j = 0; j < C; j++) {
                q[j] = fmaf(xi, sWq[h * C * C + i * C + j], q[j]);
                k[j] = fmaf(xi, sWk[h * C * C + i * C + j], k[j]);
            }
        }
        float* qp = g_q + gi * C;
        float* kp = g_k + gi * C;
#pragma unroll
        for (int j = 0; j < C; j++) {
            qp[j] = q[j]; kp[j] = k[j];
            kn2 = fmaf(k[j], k[j], kn2);
        }

        // u-vectors (fast path): u0/u1[j] = sum_c Sf[c]*x[c]*Wo[c][j]
        float u0[C2], u1[C2];
#pragma unroll
        for (int j = 0; j < C2; j++) { u0[j] = 0.f; u1[j] = 0.f; }
#pragma unroll
        for (int c = 0; c < C; c++) {
            float xc = x[c];
            float s0 = sS0f[h][c] * xc;
            float s1 = sS1f[h][c] * xc;
            const float* wo = sWo + h * C * C2 + c * C2;
#pragma unroll
            for (int j = 0; j < C2; j++) {
                u0[j] = fmaf(s0, wo[j], u0[j]);
                u1[j] = fmaf(s1, wo[j], u1[j]);
            }
        }
        float4* up = (float4*)(g_u + gi * 16);
        up[0] = make_float4(u0[0], u0[1], u0[2], u0[3]);
        up[1] = make_float4(u0[4], u0[5], u0[6], u0[7]);
        up[2] = make_float4(u1[0], u1[1], u1[2], u1[3]);
        up[3] = make_float4(u1[4], u1[5], u1[6], u1[7]);
    }

    // warp parity-preserving max of kn2 (lane parity == h), lanes 0/1 commit
#pragma unroll
    for (int ofs = 16; ofs >= 2; ofs >>= 1)
        kn2 = fmaxf(kn2, __shfl_xor_sync(0xffffffffu, kn2, ofs));
    if ((tid & 31) < 2)
        atomicMax(&g_km2[h], __float_as_uint(kn2));   // kn2 >= 0: bit order ok
}

// ---------------- kernel 2: SINGLE edge pass (inline m' bound) --------------
__global__ void __launch_bounds__(256)
k_edge(const float* __restrict__ Wo) {
    int e = blockIdx.x * blockDim.x + threadIdx.x;   // 625*256 == 160000
    int fast = g_fast;

    uint2 est = g_est[e];
    float d = __uint_as_float(est.x);
    int s = (int)(est.y & 0xffffu);
    int t = (int)(est.y >> 16);
    float d2i = 1.0f / (d * d);
    float df_h[NH] = { d, d2i };

    // global d-range -> per-head df-range
    float dhi = __uint_as_float(g_dmaxg);
    float dlo = __uint_as_float(~g_dmingX);
    float flo_h[NH] = { dlo, 1.0f / (dhi * dhi) };
    float fhi_h[NH] = { dhi, 1.0f / (dlo * dlo) };
    float km_h[NH]  = { sqrtf(__uint_as_float(g_km2[0])),
                        sqrtf(__uint_as_float(g_km2[1])) };

    if (fast) {
        float lg_h[NH], mp_h[NH];
#pragma unroll
        for (int h = 0; h < NH; h++) {
            float df = df_h[h];
            float A0 = g_A0[h][HID], A1 = g_A1[h][HID];
            float ab = fmaf(df, A1, A0);
            const float4* qt = (const float4*)(g_q + (t * NH + h) * C);
            const float4* ks = (const float4*)(g_k + (s * NH + h) * C);
            float dot = 0.f, qn2 = 0.f;
#pragma unroll
            for (int i4 = 0; i4 < 4; i4++) {
                float4 a = qt[i4], b = ks[i4];
                dot += a.x * b.x + a.y * b.y + a.z * b.z + a.w * b.w;
                qn2 += a.x * a.x + a.y * a.y + a.z * a.z + a.w * a.w;
            }
            lg_h[h] = fmaf(dot, 0.25f, ab);
            float abmax = fmaxf(fmaf(flo_h[h], A1, A0), fmaf(fhi_h[h], A1, A0));
            mp_h[h] = abmax + sqrtf(qn2) * km_h[h] * 0.25f;
        }
        const float4* up = (const float4*)(g_u + s * NH * 16);
#pragma unroll
        for (int h = 0; h < NH; h++) {
            float ex = __expf(lg_h[h] - mp_h[h]);
            red_f(&g_z[t * NH + h], ex);
            float df = df_h[h];
            float4 u0l = up[h * 4 + 0], u0h = up[h * 4 + 1];
            float4 u1l = up[h * 4 + 2], u1h = up[h * 4 + 3];
            float4 plo, phi;
            plo.x = ex * fmaf(df, u1l.x, u0l.x);
            plo.y = ex * fmaf(df, u1l.y, u0l.y);
            plo.z = ex * fmaf(df, u1l.z, u0l.z);
            plo.w = ex * fmaf(df, u1l.w, u0l.w);
            phi.x = ex * fmaf(df, u1h.x, u0h.x);
            phi.y = ex * fmaf(df, u1h.y, u0h.y);
            phi.z = ex * fmaf(df, u1h.z, u0h.z);
            phi.w = ex * fmaf(df, u1h.w, u0h.w);
            float* accp = g_accp + (t * NH + h) * C2;
            red_v4(accp,     plo);
            red_v4(accp + 4, phi);
        }
        return;
    }

    // ---- general slow path (per-edge table walk; unused for this dataset) ---
    float xs[C];
    {
        const float4* xp = (const float4*)(g_x + s * C);
#pragma unroll
        for (int i4 = 0; i4 < 4; i4++) {
            float4 v = xp[i4];
            xs[i4 * 4 + 0] = v.x; xs[i4 * 4 + 1] = v.y;
            xs[i4 * 4 + 2] = v.z; xs[i4 * 4 + 3] = v.w;
        }
    }
#pragma unroll
    for (int h = 0; h < NH; h++) {
        float df = df_h[h];
        int idx = bsearch64g(&g_t[h][0], df);
        float ab = fmaf(df, __ldg(&g_A1[h][idx]), __ldg(&g_A0[h][idx]));
        const float4* qt = (const float4*)(g_q + (t * NH + h) * C);
        const float4* ks = (const float4*)(g_k + (s * NH + h) * C);
        float dot = 0.f, qn2 = 0.f;
#pragma unroll
        for (int i4 = 0; i4 < 4; i4++) {
            float4 a = qt[i4], b = ks[i4];
            dot += a.x * b.x + a.y * b.y + a.z * b.z + a.w * b.w;
            qn2 += a.x * a.x + a.y * a.y + a.z * a.z + a.w * a.w;
        }
        float lg = fmaf(dot, 0.25f, ab);

        float flo = flo_h[h], fhi = fhi_h[h];
        int ilo = bsearch64g(&g_t[h][0], flo);
        int ihi = bsearch64g(&g_t[h][0], fhi);
        float abmax = fmaxf(fmaf(flo, __ldg(&g_A1[h][ilo]), __ldg(&g_A0[h][ilo])),
                            fmaf(fhi, __ldg(&g_A1[h][ihi]), __ldg(&g_A0[h][ihi])));
        for (int i = ilo; i < ihi; i++) {
            float tb = __ldg(&g_t[h][i]);
            abmax = fmaxf(abmax, fmaf(tb, __ldg(&g_A1[h][i + 1]), __ldg(&g_A0[h][i + 1])));
        }
        float mp = abmax + sqrtf(qn2) * km_h[h] * 0.25f;

        float ex = __expf(lg - mp);
        red_f(&g_z[t * NH + h], ex);
        const float* p0 = &g_S0[h][idx][0];
        const float* p1 = &g_S1[h][idx][0];
        float p[C2];
#pragma unroll
        for (int j = 0; j < C2; j++) p[j] = 0.f;
#pragma unroll
        for (int c = 0; c < C; c++) {
            float w = fmaf(df, __ldg(p1 + c), __ldg(p0 + c)) * xs[c];
            const float* wo = Wo + h * 3 * C * C2 + c * C2;
#pragma unroll
            for (int j = 0; j < C2; j++) p[j] = fmaf(w, __ldg(wo + j), p[j]);
        }
        float* accp = g_accp + (t * NH + h) * C2;
        red_v4(accp,     make_float4(ex * p[0], ex * p[1], ex * p[2], ex * p[3]));
        red_v4(accp + 4, make_float4(ex * p[4], ex * p[5], ex * p[6], ex * p[7]));
    }
}

// ---------------- kernel 3: normalize + pool + fused final projection -------
__global__ void __launch_bounds__(256)
k_node_out(const int* __restrict__ batch,
           const float* __restrict__ Wproj,
           const float* __restrict__ bproj,
           float* __restrict__ out) {
    int tid  = threadIdx.x;
    int gi   = blockIdx.x * blockDim.x + tid;      // (n,h) pair index
    int lane = tid & 31;

    int n = gi >> 1;
    int h = gi & 1;
    bool valid = (gi < NPAIR);

    float v[C2];
#pragma unroll
    for (int j = 0; j < C2; j++) v[j] = 0.f;
    int g = 0;
    if (valid) {
        g = batch[n];
        float z = g_z[n * NH + h];
        if (z > 0.f) {
            float inv = 1.0f / z;
            const float4* ap = (const float4*)(g_accp + (n * NH + h) * C2);
            float4 a0 = ap[0], a1 = ap[1];
            v[0] = a0.x * inv; v[1] = a0.y * inv; v[2] = a0.z * inv; v[3] = a0.w * inv;
            v[4] = a1.x * inv; v[5] = a1.y * inv; v[6] = a1.z * inv; v[7] = a1.w * inv;
        }
    }

    int g0 = __shfl_sync(0xffffffffu, g, 0);
    bool uniform = __all_sync(0xffffffffu, valid && (g == g0));
    if (uniform) {
#pragma unroll
        for (int j = 0; j < C2; j++) {
#pragma unroll
            for (int ofs = 16; ofs >= 2; ofs >>= 1)
                v[j] += __shfl_xor_sync(0xffffffffu, v[j], ofs);
        }
        if (lane < 2) {   // lane0: h=0 sums; lane1: h=1 sums
            float* dst = g_pooled + (g0 * NH + h) * C2;
            red_v4(dst,     make_float4(v[0], v[1], v[2], v[3]));
            red_v4(dst + 4, make_float4(v[4], v[5], v[6], v[7]));
        }
    } else if (valid) {
        float* dst = g_pooled + (g * NH + h) * C2;
#pragma unroll
        for (int jj = 0; jj < C2; jj++) {
            int j = (jj + lane) & (C2 - 1);
            red_f(dst + j, v[j]);
        }
    }

    // ---- last-block-done: fused final projection ----
    __shared__ int s_last;
    __threadfence();
    if (tid == 0) {
        int done = atomicAdd(&g_cnt, 1);
        s_last = (done == NO_BLOCKS - 1);
    }
    __syncthreads();
    if (s_last) {
        __threadfence();
#pragma unroll
        for (int r = 0; r < 2; r++) {
            int idx = tid + r * 256;          // 512 outputs
            int gg = idx / F_OUT;
            int oo = idx % F_OUT;
            float acc = bproj[oo];
#pragma unroll
            for (int t2 = 0; t2 < NH * C2; t2++)
                acc = fmaf(g_pooled[gg * (NH * C2) + t2], Wproj[t2 * F_OUT + oo], acc);
            out[gg * F_OUT + oo] = acc;
        }
    }
}

// ---------------- launch ----------------------------------------------------
extern "C" void kernel_launch(void* const* d_in, const int* in_sizes, int n_in,
                              void* d_out, int out_size) {
    const float* NF    = (const float*)d_in[0];
    const float* pos   = (const float*)d_in[1];
    const float* We    = (const float*)d_in[2];
    const float* be    = (const float*)d_in[3];
    const float* Wq    = (const float*)d_in[4];
    const float* Wk    = (const float*)d_in[5];
    const float* W1    = (const float*)d_in[6];
    const float* b1    = (const float*)d_in[7];
    const float* Wa    = (const float*)d_in[8];
    const float* Wv    = (const float*)d_in[9];
    const float* Wo    = (const float*)d_in[10];
    const float* Wproj = (const float*)d_in[11];
    const float* bproj = (const float*)d_in[12];
    const int*   ei    = (const int*)d_in[13];
    const int*   batch = (const int*)d_in[14];
    float* out = (float*)d_out;

    k_front<<<PAIR_BLOCKS + 1 + DIST_BLOCKS, 256>>>(NF, We, be, Wq, Wk,
                                                    W1, b1, Wa, Wv, Wo, pos, ei);
    k_edge<<<EL_BLOCKS, 256>>>(Wo);
    k_node_out<<<NO_BLOCKS, 256>>>(batch, Wproj, bproj, out);
}

// round 15
// speedup vs baseline: 1.7221x; 1.2200x over previous
#include <cuda_runtime.h>

#define N_NODES 10000
#define N_EDGES 160000
#define E_Q     40000
#define C       16
#define C2      8
#define HID     64
#define NH      2
#define NG      16
#define F_IN    64
#define F_OUT   32
#define NI      65   // intervals = HID+1

#define NPAIR       (N_NODES * NH)        // 20000
#define PAIR_BLOCKS ((NPAIR + 255) / 256) // 79
#define DIST_BLOCKS 157                   // ceil(40000/256), 4 edges/thread
#define EL_BLOCKS   625                   // 1 edge/thread, 625*256 = 160000
#define NO_BLOCKS   PAIR_BLOCKS           // 79

// ---------------- scratch (device globals; no allocations allowed) ----------
__device__ __align__(16) float g_x[N_NODES * C];                 // [n][c]
__device__ __align__(16) float g_q[NPAIR * C];                   // [n*2+h][c]
__device__ __align__(128) float g_sk[NPAIR * 32];                // [pair][k(16),u0(8),u1(8)]
__device__ __align__(8) uint2 g_est[N_EDGES];                    // {bits(dist), s|t<<16}
__device__ unsigned g_dmaxg;             // global max d bits   (idempotent across replays)
__device__ unsigned g_dmingX;            // global max ~bits(d) (~ => min d)
__device__ unsigned g_km2[NH];           // global max |k|^2 bits per head
__device__ __align__(8) float    g_z[N_NODES * NH];              // [n][h]
__device__ __align__(16) float g_accp[N_NODES * NH * C2];        // projected acc [n][h][j]
__device__ float    g_pooled[NG * NH * C2];
__device__ int      g_cnt;
__device__ int      g_fast;

// piecewise-linear tables (slow fallback path only)
__device__ float g_t [NH][HID];      // sorted breakpoints
__device__ __align__(16) float g_S0[NH][NI][C];
__device__ __align__(16) float g_S1[NH][NI][C];
__device__ float g_A0[NH][NI];
__device__ float g_A1[NH][NI];

__device__ __forceinline__ void red_v4(float* p, float4 v) {
    asm volatile("red.global.add.v4.f32 [%0], {%1, %2, %3, %4};"
                 :: "l"(p), "f"(v.x), "f"(v.y), "f"(v.z), "f"(v.w) : "memory");
}
__device__ __forceinline__ void red_v2(float* p, float2 v) {
    asm volatile("red.global.add.v2.f32 [%0], {%1, %2};"
                 :: "l"(p), "f"(v.x), "f"(v.y) : "memory");
}
__device__ __forceinline__ void red_f(float* p, float v) {
    asm volatile("red.global.add.f32 [%0], %1;" :: "l"(p), "f"(v) : "memory");
}

// binary search (global-memory breakpoints; slow path only)
__device__ __forceinline__ int bsearch64g(const float* t, float df) {
    int lo = 0, hi = HID;
#pragma unroll
    for (int it = 0; it < 7; it++) {
        if (lo < hi) {
            int mid = (lo + hi) >> 1;
            if (__ldg(t + mid) < df) lo = mid + 1; else hi = mid;
        }
    }
    return lo;
}

// ---------------- kernel 1: nodes(+u) + table block + edge-dist blocks ------
__global__ void __launch_bounds__(256)
k_front(const float* __restrict__ NF,
        const float* __restrict__ We,
        const float* __restrict__ be,
        const float* __restrict__ Wq,
        const float* __restrict__ Wk,
        const float* __restrict__ W1,
        const float* __restrict__ b1,
        const float* __restrict__ Wa,
        const float* __restrict__ Wv,
        const float* __restrict__ Wo,
        const float* __restrict__ pos,
        const int* __restrict__ ei) {
    int tid = threadIdx.x;
    int bid = blockIdx.x;

    if (bid > PAIR_BLOCKS) {
        // ---- edge geometry blocks: 4 edges/thread, dist + s|t + d-range ----
        int i = (bid - PAIR_BLOCKS - 1) * 256 + tid;
        unsigned lmax = 0u, lminX = 0u;
        if (i < E_Q) {
#pragma unroll
            for (int u = 0; u < 4; u++) {
                int e = i + u * E_Q;
                int s = ei[e];
                int t = ei[N_EDGES + e];
                float dx = pos[3 * t + 0] - pos[3 * s + 0];
                float dy = pos[3 * t + 1] - pos[3 * s + 1];
                float dz = pos[3 * t + 2] - pos[3 * s + 2];
                float d2 = dx * dx + dy * dy + dz * dz;
                float d  = sqrtf(d2);
                unsigned db = __float_as_uint(d);    // d > 0: bit order == float order
                g_est[e] = make_uint2(db, (unsigned)s | ((unsigned)t << 16));
                lmax  = max(lmax, db);
                lminX = max(lminX, ~db);
            }
        }
        // warp reduce then 1 atomic per warp per counter
#pragma unroll
        for (int ofs = 16; ofs >= 1; ofs >>= 1) {
            lmax  = max(lmax,  __shfl_xor_sync(0xffffffffu, lmax,  ofs));
            lminX = max(lminX, __shfl_xor_sync(0xffffffffu, lminX, ofs));
        }
        if ((tid & 31) == 0) {
            atomicMax(&g_dmaxg,  lmax);
            atomicMax(&g_dmingX, lminX);
        }
        return;
    }

    if (bid == PAIR_BLOCKS) {
        // ---- table block: fast detection + (fast: top-interval only) -------
        __shared__ int s_fast;
        __shared__ unsigned sany[8];
        __shared__ float sA0w[4], sA1w[4];
        if (tid == 0) g_cnt = 0;

        int pos_bp = 0;
        if (tid < NH * HID) {
            int h = tid / HID, j = tid % HID;
            float w = W1[h * HID + j], b = b1[h * HID + j];
            pos_bp = (w != 0.f) && ((-b / w) > 0.f);   // breakpoint strictly > 0?
        }
        unsigned any = __ballot_sync(0xffffffffu, pos_bp);
        if ((tid & 31) == 0) sany[tid >> 5] = any;
        __syncthreads();
        if (tid == 0) {
            unsigned tot = 0;
            for (int wgi = 0; wgi < 8; wgi++) tot |= sany[wgi];
            s_fast = (tot == 0u) ? 1 : 0;
            g_fast = s_fast;
        }
        __syncthreads();

        if (s_fast) {
            // only A0/A1 at top interval are consumed by the fast path
            float a0 = 0.f, a1 = 0.f;
            if (tid < NH * HID) {
                int h = tid / HID, j = tid % HID;
                float w = W1[h * HID + j], b = b1[h * HID + j];
                if ((w > 0.f) || (w == 0.f && b > 0.f)) {   // active as df -> +inf
                    float wa = Wa[h * HID + j];
                    a0 = b * wa;
                    a1 = w * wa;
                }
            }
#pragma unroll
            for (int ofs = 16; ofs >= 1; ofs >>= 1) {
                a0 += __shfl_xor_sync(0xffffffffu, a0, ofs);
                a1 += __shfl_xor_sync(0xffffffffu, a1, ofs);
            }
            if ((tid & 31) == 0 && tid < 128) { sA0w[tid >> 5] = a0; sA1w[tid >> 5] = a1; }
            __syncthreads();
            if (tid < NH) {
                g_A0[tid][HID] = sA0w[tid * 2] + sA0w[tid * 2 + 1];
                g_A1[tid][HID] = sA1w[tid * 2] + sA1w[tid * 2 + 1];
            }
        } else {
            // ---- full table build (slow path; not taken for this dataset) ----
            __shared__ float raw[NH][HID];
            __shared__ float stt[NH][HID];
            if (tid < NH * HID) {
                int h = tid / HID, j = tid % HID;
                float w = W1[h * HID + j], b = b1[h * HID + j];
                raw[h][j] = (w != 0.f) ? (-b / w) : -1e30f;
            }
            __syncthreads();
            if (tid < NH * HID) {
                int h = tid / HID, j = tid % HID;
                float v = raw[h][j];
                int rank = 0;
                for (int i = 0; i < HID; i++) {
                    float o = raw[h][i];
                    rank += (o < v || (o == v && i < j)) ? 1 : 0;
                }
                stt[h][rank] = v;
                g_t[h][rank] = v;
            }
            __syncthreads();
            if (tid < NH * NI) {
                int h = tid / NI, i = tid % NI;
                float lo = (i == 0)   ? stt[h][0] - 1.0f       : stt[h][i - 1];
                float hi = (i == HID) ? stt[h][HID - 1] + 1.0f : stt[h][i];
                float mid = 0.5f * (lo + hi);
                float S0[C], S1[C], A0 = 0.f, A1 = 0.f;
#pragma unroll
                for (int c = 0; c < C; c++) { S0[c] = 0.f; S1[c] = 0.f; }
                for (int j = 0; j < HID; j++) {
                    float w = W1[h * HID + j], b = b1[h * HID + j];
                    bool act;
                    if (i == HID) act = (w > 0.f) || (w == 0.f && b > 0.f);
                    else          act = fmaf(w, mid, b) > 0.f;
                    if (act) {
                        float wa = Wa[h * HID + j];
                        A0 = fmaf(b, wa, A0);
                        A1 = fmaf(w, wa, A1);
#pragma unroll
                        for (int c = 0; c < C; c++) {
                            float wv = Wv[(h * HID + j) * (C * 3) + 3 * c];
                            S0[c] = fmaf(b, wv, S0[c]);
                            S1[c] = fmaf(w, wv, S1[c]);
                        }
                    }
                }
#pragma unroll
                for (int c = 0; c < C; c++) { g_S0[h][i][c] = S0[c]; g_S1[h][i][c] = S1[c]; }
                g_A0[h][i] = A0; g_A1[h][i] = A1;
            }
        }
        if (tid < NG * NH * C2) g_pooled[tid] = 0.f;
        return;
    }

    // ---- node-pair blocks: one thread per (n, h); also computes u-vectors --
    __shared__ float sWe[F_IN * C];
    __shared__ float sbe[C];
    __shared__ float sWq[NH * C * C];
    __shared__ float sWk[NH * C * C];
    __shared__ float sWo[NH * C * C2];            // li=0 slice [h][c][j]
    __shared__ float sP0[NH][C][8], sP1[NH][C][8]; // partials for fast S rows
    __shared__ float sS0f[NH][C], sS1f[NH][C];     // fast-path (top-interval) rows
    for (int i = tid; i < F_IN * C; i += blockDim.x) sWe[i] = We[i];
    for (int i = tid; i < C; i += blockDim.x) sbe[i] = be[i];
    for (int i = tid; i < NH * C * C; i += blockDim.x) { sWq[i] = Wq[i]; sWk[i] = Wk[i]; }
    for (int i = tid; i < NH * C * C2; i += blockDim.x) {
        int h = i / (C * C2);
        int r = i % (C * C2);
        sWo[i] = Wo[h * 3 * C * C2 + r];
    }
    {
        // parallel fast-S-row build: thread = (h, c, jgroup of 8)
        int h  = tid >> 7;            // 0..1
        int c  = (tid >> 3) & 15;     // 0..15
        int gq = tid & 7;             // 0..7
        float p0 = 0.f, p1 = 0.f;
#pragma unroll
        for (int jj = 0; jj < 8; jj++) {
            int j = gq * 8 + jj;
            float w = W1[h * HID + j], b = b1[h * HID + j];
            if ((w > 0.f) || (w == 0.f && b > 0.f)) {   // active as df -> +inf
                float wv = Wv[(h * HID + j) * (C * 3) + 3 * c];
                p0 = fmaf(b, wv, p0);
                p1 = fmaf(w, wv, p1);
            }
        }
        sP0[h][c][gq] = p0;
        sP1[h][c][gq] = p1;
    }
    __syncthreads();
    if (tid < NH * C) {
        int h = tid / C, c = tid % C;
        float s0 = 0.f, s1 = 0.f;
#pragma unroll
        for (int gq = 0; gq < 8; gq++) { s0 += sP0[h][c][gq]; s1 += sP1[h][c][gq]; }
        sS0f[h][c] = s0;
        sS1f[h][c] = s1;
    }
    __syncthreads();

    int gi = bid * blockDim.x + tid;
    bool valid = (gi < NPAIR);
    int n = gi >> 1;
    int h = gi & 1;
    float kn2 = 0.f;

    if (valid) {
        if (h == 0) {
            *(float2*)(g_z + n * NH) = make_float2(0.f, 0.f);
            float4 zf4 = make_float4(0.f, 0.f, 0.f, 0.f);
            float4* ac = (float4*)(g_accp + n * NH * C2);
#pragma unroll
            for (int i = 0; i < 4; i++) ac[i] = zf4;
        }

        float x[C];
#pragma unroll
        for (int j = 0; j < C; j++) x[j] = sbe[j];
        const float4* nf4 = (const float4*)(NF + n * F_IN);
#pragma unroll
        for (int i4 = 0; i4 < F_IN / 4; i4++) {
            float4 v = nf4[i4];
            float vs[4] = { v.x, v.y, v.z, v.w };
#pragma unroll
            for (int k = 0; k < 4; k++) {
                float vv = vs[k];
                int i = i4 * 4 + k;
#pragma unroll
                for (int j = 0; j < C; j++) x[j] = fmaf(vv, sWe[i * C + j], x[j]);
            }
        }
        if (h == 0) {
#pragma unroll
            for (int j = 0; j < C; j++) g_x[n * C + j] = x[j];
        }

        float q[C], k[C];
#pragma unroll
        for (int j = 0; j < C; j++) { q[j] = 0.f; k[j] = 0.f; }
#pragma unroll
        for (int i = 0; i < C; i++) {
            float xi = x[i];
#pragma unroll
            for (int j = 0; j < C; j++) {
                q[j] = fmaf(xi, sWq[h * C * C + i * C + j], q[j]);
                k[j] = fmaf(xi, sWk[h * C * C + i * C + j], k[j]);
            }
        }
        float* qp = g_q + gi * C;
        float* kp = g_sk + gi * 32;          // k slot of packed record
#pragma unroll
        for (int j = 0; j < C; j++) {
            qp[j] = q[j]; kp[j] = k[j];
            kn2 = fmaf(k[j], k[j], kn2);
        }

        // u-vectors (fast path): u0/u1[j] = sum_c Sf[c]*x[c]*Wo[c][j]
        float u0[C2], u1[C2];
#pragma unroll
        for (int j = 0; j < C2; j++) { u0[j] = 0.f; u1[j] = 0.f; }
#pragma unroll
        for (int c = 0; c < C; c++) {
            float xc = x[c];
            float s0 = sS0f[h][c] * xc;
            float s1 = sS1f[h][c] * xc;
            const float* wo = sWo + h * C * C2 + c * C2;
#pragma unroll
            for (int j = 0; j < C2; j++) {
                u0[j] = fmaf(s0, wo[j], u0[j]);
                u1[j] = fmaf(s1, wo[j], u1[j]);
            }
        }
        float4* up = (float4*)(g_sk + gi * 32 + 16);   // u slots of packed record
        up[0] = make_float4(u0[0], u0[1], u0[2], u0[3]);
        up[1] = make_float4(u0[4], u0[5], u0[6], u0[7]);
        up[2] = make_float4(u1[0], u1[1], u1[2], u1[3]);
        up[3] = make_float4(u1[4], u1[5], u1[6], u1[7]);
    }

    // warp parity-preserving max of kn2 (lane parity == h), lanes 0/1 commit
#pragma unroll
    for (int ofs = 16; ofs >= 2; ofs >>= 1)
        kn2 = fmaxf(kn2, __shfl_xor_sync(0xffffffffu, kn2, ofs));
    if ((tid & 31) < 2)
        atomicMax(&g_km2[h], __float_as_uint(kn2));   // kn2 >= 0: bit order ok
}

// ---------------- kernel 2: SINGLE edge pass (inline m' bound) --------------
__global__ void __launch_bounds__(256)
k_edge(const float* __restrict__ Wo) {
    int e = blockIdx.x * blockDim.x + threadIdx.x;   // 625*256 == 160000
    int fast = g_fast;

    uint2 est = g_est[e];
    float d = __uint_as_float(est.x);
    int s = (int)(est.y & 0xffffu);
    int t = (int)(est.y >> 16);
    float d2i = 1.0f / (d * d);
    float df_h[NH] = { d, d2i };

    // global d-range -> per-head df-range
    float dhi = __uint_as_float(g_dmaxg);
    float dlo = __uint_as_float(~g_dmingX);
    float flo_h[NH] = { dlo, 1.0f / (dhi * dhi) };
    float fhi_h[NH] = { dhi, 1.0f / (dlo * dlo) };
    float km_h[NH]  = { sqrtf(__uint_as_float(g_km2[0])),
                        sqrtf(__uint_as_float(g_km2[1])) };

    if (fast) {
        float ex_h[NH], sk[NH][8][4];   // per-head packed record (k,u0,u1) as float4s
#pragma unroll
        for (int h = 0; h < NH; h++) {
            float df = df_h[h];
            float A0 = g_A0[h][HID], A1 = g_A1[h][HID];
            float ab = fmaf(df, A1, A0);
            const float4* qt  = (const float4*)(g_q  + (t * NH + h) * C);
            const float4* skp = (const float4*)(g_sk + (s * NH + h) * 32);
            float4 kv[4];
#pragma unroll
            for (int i4 = 0; i4 < 8; i4++) {
                float4 v = skp[i4];
                sk[h][i4][0] = v.x; sk[h][i4][1] = v.y;
                sk[h][i4][2] = v.z; sk[h][i4][3] = v.w;
                if (i4 < 4) kv[i4] = v;
            }
            float dot = 0.f, qn2 = 0.f;
#pragma unroll
            for (int i4 = 0; i4 < 4; i4++) {
                float4 a = qt[i4], b = kv[i4];
                dot += a.x * b.x + a.y * b.y + a.z * b.z + a.w * b.w;
                qn2 += a.x * a.x + a.y * a.y + a.z * a.z + a.w * a.w;
            }
            float lg = fmaf(dot, 0.25f, ab);
            float abmax = fmaxf(fmaf(flo_h[h], A1, A0), fmaf(fhi_h[h], A1, A0));
            float mp = abmax + sqrtf(qn2) * km_h[h] * 0.25f;
            ex_h[h] = __expf(lg - mp);
        }
        red_v2(&g_z[t * NH], make_float2(ex_h[0], ex_h[1]));
#pragma unroll
        for (int h = 0; h < NH; h++) {
            float ex = ex_h[h];
            float df = df_h[h];
            float4 plo, phi;
            plo.x = ex * fmaf(df, sk[h][6][0], sk[h][4][0]);
            plo.y = ex * fmaf(df, sk[h][6][1], sk[h][4][1]);
            plo.z = ex * fmaf(df, sk[h][6][2], sk[h][4][2]);
            plo.w = ex * fmaf(df, sk[h][6][3], sk[h][4][3]);
            phi.x = ex * fmaf(df, sk[h][7][0], sk[h][5][0]);
            phi.y = ex * fmaf(df, sk[h][7][1], sk[h][5][1]);
            phi.z = ex * fmaf(df, sk[h][7][2], sk[h][5][2]);
            phi.w = ex * fmaf(df, sk[h][7][3], sk[h][5][3]);
            float* accp = g_accp + (t * NH + h) * C2;
            red_v4(accp,     plo);
            red_v4(accp + 4, phi);
        }
        return;
    }

    // ---- general slow path (per-edge table walk; unused for this dataset) ---
    float xs[C];
    {
        const float4* xp = (const float4*)(g_x + s * C);
#pragma unroll
        for (int i4 = 0; i4 < 4; i4++) {
            float4 v = xp[i4];
            xs[i4 * 4 + 0] = v.x; xs[i4 * 4 + 1] = v.y;
            xs[i4 * 4 + 2] = v.z; xs[i4 * 4 + 3] = v.w;
        }
    }
#pragma unroll
    for (int h = 0; h < NH; h++) {
        float df = df_h[h];
        int idx = bsearch64g(&g_t[h][0], df);
        float ab = fmaf(df, __ldg(&g_A1[h][idx]), __ldg(&g_A0[h][idx]));
        const float4* qt = (const float4*)(g_q + (t * NH + h) * C);
        const float4* ks = (const float4*)(g_sk + (s * NH + h) * 32);
        float dot = 0.f, qn2 = 0.f;
#pragma unroll
        for (int i4 = 0; i4 < 4; i4++) {
            float4 a = qt[i4], b = ks[i4];
            dot += a.x * b.x + a.y * b.y + a.z * b.z + a.w * b.w;
            qn2 += a.x * a.x + a.y * a.y + a.z * a.z + a.w * a.w;
        }
        float lg = fmaf(dot, 0.25f, ab);

        float flo = flo_h[h], fhi = fhi_h[h];
        int ilo = bsearch64g(&g_t[h][0], flo);
        int ihi = bsearch64g(&g_t[h][0], fhi);
        float abmax = fmaxf(fmaf(flo, __ldg(&g_A1[h][ilo]), __ldg(&g_A0[h][ilo])),
                            fmaf(fhi, __ldg(&g_A1[h][ihi]), __ldg(&g_A0[h][ihi])));
        for (int i = ilo; i < ihi; i++) {
            float tb = __ldg(&g_t[h][i]);
            abmax = fmaxf(abmax, fmaf(tb, __ldg(&g_A1[h][i + 1]), __ldg(&g_A0[h][i + 1])));
        }
        float mp = abmax + sqrtf(qn2) * km_h[h] * 0.25f;

        float ex = __expf(lg - mp);
        red_f(&g_z[t * NH + h], ex);
        const float* p0 = &g_S0[h][idx][0];
        const float* p1 = &g_S1[h][idx][0];
        float p[C2];
#pragma unroll
        for (int j = 0; j < C2; j++) p[j] = 0.f;
#pragma unroll
        for (int c = 0; c < C; c++) {
            float w = fmaf(df, __ldg(p1 + c), __ldg(p0 + c)) * xs[c];
            const float* wo = Wo + h * 3 * C * C2 + c * C2;
#pragma unroll
            for (int j = 0; j < C2; j++) p[j] = fmaf(w, __ldg(wo + j), p[j]);
        }
        float* accp = g_accp + (t * NH + h) * C2;
        red_v4(accp,     make_float4(ex * p[0], ex * p[1], ex * p[2], ex * p[3]));
        red_v4(accp + 4, make_float4(ex * p[4], ex * p[5], ex * p[6], ex * p[7]));
    }
}

// ---------------- kernel 3: normalize + pool + fused final projection -------
__global__ void __launch_bounds__(256)
k_node_out(const int* __restrict__ batch,
           const float* __restrict__ Wproj,
           const float* __restrict__ bproj,
           float* __restrict__ out) {
    int tid  = threadIdx.x;
    int gi   = blockIdx.x * blockDim.x + tid;      // (n,h) pair index
    int lane = tid & 31;

    int n = gi >> 1;
    int h = gi & 1;
    bool valid = (gi < NPAIR);

    float v[C2];
#pragma unroll
    for (int j = 0; j < C2; j++) v[j] = 0.f;
    int g = 0;
    if (valid) {
        g = batch[n];
        float z = g_z[n * NH + h];
        if (z > 0.f) {
            float inv = 1.0f / z;
            const float4* ap = (const float4*)(g_accp + (n * NH + h) * C2);
            float4 a0 = ap[0], a1 = ap[1];
            v[0] = a0.x * inv; v[1] = a0.y * inv; v[2] = a0.z * inv; v[3] = a0.w * inv;
            v[4] = a1.x * inv; v[5] = a1.y * inv; v[6] = a1.z * inv; v[7] = a1.w * inv;
        }
    }

    int g0 = __shfl_sync(0xffffffffu, g, 0);
    bool uniform = __all_sync(0xffffffffu, valid && (g == g0));
    if (uniform) {
#pragma unroll
        for (int j = 0; j < C2; j++) {
#pragma unroll
            for (int ofs = 16; ofs >= 2; ofs >>= 1)
                v[j] += __shfl_xor_sync(0xffffffffu, v[j], ofs);
        }
        if (lane < 2) {   // lane0: h=0 sums; lane1: h=1 sums
            float* dst = g_pooled + (g0 * NH + h) * C2;
            red_v4(dst,     make_float4(v[0], v[1], v[2], v[3]));
            red_v4(dst + 4, make_float4(v[4], v[5], v[6], v[7]));
        }
    } else if (valid) {
        float* dst = g_pooled + (g * NH + h) * C2;
#pragma unroll
        for (int jj = 0; jj < C2; jj++) {
            int j = (jj + lane) & (C2 - 1);
            red_f(dst + j, v[j]);
        }
    }

    // ---- last-block-done: fused final projection ----
    __shared__ int s_last;
    __threadfence();
    if (tid == 0) {
        int done = atomicAdd(&g_cnt, 1);
        s_last = (done == NO_BLOCKS - 1);
    }
    __syncthreads();
    if (s_last) {
        __threadfence();
#pragma unroll
        for (int r = 0; r < 2; r++) {
            int idx = tid + r * 256;          // 512 outputs
            int gg = idx / F_OUT;
            int oo = idx % F_OUT;
            float acc = bproj[oo];
#pragma unroll
            for (int t2 = 0; t2 < NH * C2; t2++)
                acc = fmaf(g_pooled[gg * (NH * C2) + t2], Wproj[t2 * F_OUT + oo], acc);
            out[gg * F_OUT + oo] = acc;
        }
    }
}

// ---------------- launch ----------------------------------------------------
extern "C" void kernel_launch(void* const* d_in, const int* in_sizes, int n_in,
                              void* d_out, int out_size) {
    const float* NF    = (const float*)d_in[0];
    const float* pos   = (const float*)d_in[1];
    const float* We    = (const float*)d_in[2];
    const float* be    = (const float*)d_in[3];
    const float* Wq    = (const float*)d_in[4];
    const float* Wk    = (const float*)d_in[5];
    const float* W1    = (const float*)d_in[6];
    const float* b1    = (const float*)d_in[7];
    const float* Wa    = (const float*)d_in[8];
    const float* Wv    = (const float*)d_in[9];
    const float* Wo    = (const float*)d_in[10];
    const float* Wproj = (const float*)d_in[11];
    const float* bproj = (const float*)d_in[12];
    const int*   ei    = (const int*)d_in[13];
    const int*   batch = (const int*)d_in[14];
    float* out = (float*)d_out;

    k_front<<<PAIR_BLOCKS + 1 + DIST_BLOCKS, 256>>>(NF, We, be, Wq, Wk,
                                                    W1, b1, Wa, Wv, Wo, pos, ei);
    k_edge<<<EL_BLOCKS, 256>>>(Wo);
    k_node_out<<<NO_BLOCKS, 256>>>(batch, Wproj, bproj, out);
}